// round 6
// baseline (speedup 1.0000x reference)
#include <cuda_runtime.h>
#include <cstdint>

// Problem constants
#define H8    64
#define W8    64
#define CH    256
#define BATCH 4
#define NPIX  (H8 * W8)          // 4096
#define NL    41                 // diamond taps
#define F2P_PIX 5440             // 4096 + 1024 + 256 + 64 pooled pixels per batch

// Level pixel offsets inside g_f2p (per batch)
#define LVL0_OFF 0
#define LVL1_OFF 4096
#define LVL2_OFF 5120
#define LVL3_OFF 5376

// Scratch: transposed f1 [B][pix][C], pooled+transposed f2 pyramid [B][lvl pix][C]
__device__ __align__(16) float g_f1t[BATCH * NPIX * CH];
__device__ __align__(16) float g_f2p[BATCH * F2P_PIX * CH];

// Diamond offsets (y, x): y=-4..4, x = |y|-4 .. 4-|y|  (41 total)
__constant__ float c_dy[NL] = {
    -4.f,
    -3.f,-3.f,-3.f,
    -2.f,-2.f,-2.f,-2.f,-2.f,
    -1.f,-1.f,-1.f,-1.f,-1.f,-1.f,-1.f,
     0.f, 0.f, 0.f, 0.f, 0.f, 0.f, 0.f, 0.f, 0.f,
     1.f, 1.f, 1.f, 1.f, 1.f, 1.f, 1.f,
     2.f, 2.f, 2.f, 2.f, 2.f,
     3.f, 3.f, 3.f,
     4.f};
__constant__ float c_dx[NL] = {
     0.f,
    -1.f, 0.f, 1.f,
    -2.f,-1.f, 0.f, 1.f, 2.f,
    -3.f,-2.f,-1.f, 0.f, 1.f, 2.f, 3.f,
    -4.f,-3.f,-2.f,-1.f, 0.f, 1.f, 2.f, 3.f, 4.f,
    -3.f,-2.f,-1.f, 0.f, 1.f, 2.f, 3.f,
    -2.f,-1.f, 0.f, 1.f, 2.f,
    -1.f, 0.f, 1.f,
     0.f};

// ---------------------------------------------------------------------------
// Kernel 1: transpose [B][C][4096] -> [B][4096][C]
// ---------------------------------------------------------------------------
__global__ void transpose_kernel(const float* __restrict__ in, int which, int out_pix_stride) {
    __shared__ float tile[32][33];
    float* outp = which ? g_f2p : g_f1t;
    int b  = blockIdx.z;
    int p0 = blockIdx.x * 32;
    int c0 = blockIdx.y * 32;
    const float* inb = in + (size_t)b * CH * NPIX;
    float* outb = outp + (size_t)b * out_pix_stride * CH;
    int tx = threadIdx.x, ty = threadIdx.y;
#pragma unroll
    for (int r = 0; r < 32; r += 8)
        tile[ty + r][tx] = inb[(size_t)(c0 + ty + r) * NPIX + (p0 + tx)];
    __syncthreads();
#pragma unroll
    for (int r = 0; r < 32; r += 8)
        outb[(size_t)(p0 + ty + r) * CH + (c0 + tx)] = tile[tx][ty + r];
}

// ---------------------------------------------------------------------------
// Kernel 2: 2x2 avg pool in [y][x][C] layout (within g_f2p), per batch.
// ---------------------------------------------------------------------------
__global__ void pool_kernel(int in_off, int out_off, int ho) {
    int idx = blockIdx.x * blockDim.x + threadIdx.x;
    int c4   = idx & 63;
    int rest = idx >> 6;
    int x = rest % ho; rest /= ho;
    int y = rest % ho;
    int b = rest / ho;
    int wi = ho * 2;
    const float4* inp = (const float4*)g_f2p;
    float4*       out4 = (float4*)g_f2p;
    size_t base = ((size_t)b * F2P_PIX + in_off + (size_t)(2 * y) * wi + 2 * x) * 64 + c4;
    float4 v00 = inp[base];
    float4 v01 = inp[base + 64];
    float4 v10 = inp[base + (size_t)wi * 64];
    float4 v11 = inp[base + (size_t)wi * 64 + 64];
    float4 o;
    o.x = 0.25f * (v00.x + v01.x + v10.x + v11.x);
    o.y = 0.25f * (v00.y + v01.y + v10.y + v11.y);
    o.z = 0.25f * (v00.z + v01.z + v10.z + v11.z);
    o.w = 0.25f * (v00.w + v01.w + v10.w + v11.w);
    out4[((size_t)b * F2P_PIX + out_off + (size_t)y * ho + x) * 64 + c4] = o;
}

// ---------------------------------------------------------------------------
// Kernel 3: fused lookup.
// Block = 128 threads = 4 warps; warp owns a 2x2 pixel PATCH.
// Per level, per warp:
//   - group patch pixels whose 10x10 windows fit a common 16x16 frame
//     (offset <= 6; outlier pixels processed as singleton groups)
//   - dedupe the union of the group's diamond-tap corners via smem flags,
//     ballot-compact in-grid corners into a list
//   - dot loop: 16 lanes per corner, 2 corners per step; each loaded f2
//     chunk is FMA'd against ALL 4 pixels' f1 (registers) -> L1 traffic / 4
//   - per-pixel 10x10 D tables in smem; Phase B taps bilinear-combine them
// ---------------------------------------------------------------------------
__global__ void __launch_bounds__(128) lookup_kernel(const float* __restrict__ flow,
                                                     float* __restrict__ out) {
    const int tid  = threadIdx.x;
    const int lane = tid & 31;
    const int warp = tid >> 5;            // 0..3

    const int tile = blockIdx.x;          // 0..255 -> 4x4 pixel tile
    const int bb   = blockIdx.y;
    const int ti = tile >> 4, tj = tile & 15;
    const int i0 = ti * 4 + (warp >> 1) * 2;   // patch origin
    const int j0 = tj * 4 + (warp & 1) * 2;

    __shared__ float D[4][4][100];        // [warp][pixel][10x10]
    __shared__ short s_list[4][256];
    __shared__ unsigned char s_flag[4][256];
    __shared__ float s_dy[NL], s_dx[NL];
    if (tid < NL) { s_dy[tid] = c_dy[tid]; s_dx[tid] = c_dx[tid]; }

    // Per-pixel flow (L1-broadcast loads; all lanes read same addresses)
    float fys[4], fxs[4];
    int   ip[4], jp[4];
#pragma unroll
    for (int p = 0; p < 4; p++) {
        ip[p] = i0 + (p >> 1);
        jp[p] = j0 + (p & 1);
        fys[p] = flow[((size_t)(bb * 2 + 0) * H8 + ip[p]) * W8 + jp[p]];
        fxs[p] = flow[((size_t)(bb * 2 + 1) * H8 + ip[p]) * W8 + jp[p]];
    }

    // f1 registers: lane (s = lane&15) owns channels s*16 .. s*16+15 of all 4 px
    const int c0 = (lane & 15) << 4;
    const int g  = lane >> 4;             // corner slot 0/1
    float4 f1r[4][4];
#pragma unroll
    for (int p = 0; p < 4; p++) {
        const float* f1v = g_f1t + (((size_t)bb * NPIX + ip[p] * W8 + jp[p]) << 8) + c0;
#pragma unroll
        for (int u = 0; u < 4; u++) f1r[p][u] = *(const float4*)(f1v + 4 * u);
    }

    const int lvl_off[4] = {LVL0_OFF, LVL1_OFF, LVL2_OFF, LVL3_OFF};
    __syncthreads();

    for (int k = 0; k < 4; k++) {
        const int   hh  = H8 >> k;
        const float s   = (float)(hh - 1) / (float)hh;
        const float inv = 1.0f / (float)(1 << k);

        float ycf[4], xcf[4];
        int   oy[4], ox[4];
#pragma unroll
        for (int p = 0; p < 4; p++) {
            ycf[p] = ((float)ip[p] + fys[p]) * inv;
            xcf[p] = ((float)jp[p] + fxs[p]) * inv;
            oy[p] = (int)floorf((ycf[p] - 4.0f) * s);
            ox[p] = (int)floorf((xcf[p] - 4.0f) * s);
        }

        // Zero this warp's D tables (corners never computed must read 0)
        {
            float4* dw = (float4*)&D[warp][0][0];
#pragma unroll
            for (int t = 0; t < 4; t++)
                if (lane + t * 32 < 100) dw[lane + t * 32] = make_float4(0.f, 0.f, 0.f, 0.f);
        }
        __syncwarp();

        unsigned done = 0;
        while (done != 0xFu) {
            // group origin = min over undone; members within +6 offset
            int oyg = 1 << 28, oxg = 1 << 28;
#pragma unroll
            for (int p = 0; p < 4; p++)
                if (!((done >> p) & 1)) { oyg = min(oyg, oy[p]); oxg = min(oxg, ox[p]); }
            unsigned gm = 0;
#pragma unroll
            for (int p = 0; p < 4; p++)
                if (!((done >> p) & 1) && (oy[p] - oyg) <= 6 && (ox[p] - oxg) <= 6)
                    gm |= 1u << p;
            done |= gm;

            // ---- dedupe corners via flags in the 16x16 frame ----
            *(unsigned long long*)&s_flag[warp][lane * 8] = 0ull;
            __syncwarp();
#pragma unroll
            for (int p = 0; p < 4; p++) {
                if (!((gm >> p) & 1)) continue;
#pragma unroll
                for (int r = 0; r < 2; r++) {
                    int l = lane + r * 32;
                    if (l < NL) {
                        float py = (ycf[p] + s_dy[l]) * s;
                        float px = (xcf[p] + s_dx[l]) * s;
                        int iyf = (int)floorf(py) - oyg;     // 0..14
                        int ixf = (int)floorf(px) - oxg;     // 0..14
                        int pp = iyf * 16 + ixf;
                        s_flag[warp][pp]      = 1;
                        s_flag[warp][pp + 1]  = 1;
                        s_flag[warp][pp + 16] = 1;
                        s_flag[warp][pp + 17] = 1;
                    }
                }
            }
            __syncwarp();

            // ---- ballot-compact in-grid flagged corners ----
            int n = 0;
#pragma unroll
            for (int r = 0; r < 8; r++) {
                int cid = r * 32 + lane;
                unsigned bit = s_flag[warp][cid];
                if (bit) {
                    int y = oyg + (cid >> 4), x = oxg + (cid & 15);
                    if ((unsigned)y >= (unsigned)hh || (unsigned)x >= (unsigned)hh) bit = 0;
                }
                unsigned ball = __ballot_sync(0xFFFFFFFFu, bit);
                if (bit) s_list[warp][n + __popc(ball & ((1u << lane) - 1u))] = (short)cid;
                n += __popc(ball);
            }
            __syncwarp();

            // ---- dot loop: 2 corners per step, 4 pixels per load ----
            const float* base = g_f2p + ((size_t)bb * F2P_PIX + lvl_off[k]) * CH;
            for (int q = 0; q < n; q += 2) {
                const int idx  = q + g;
                const int cidx = idx < n ? idx : n - 1;
                const int cid  = s_list[warp][cidx];
                const int y = oyg + (cid >> 4);
                const int x = oxg + (cid & 15);
                const float* v = base + (((size_t)(y * hh + x)) << 8) + c0;

                float acc[4] = {0.f, 0.f, 0.f, 0.f};
#pragma unroll
                for (int u = 0; u < 4; u++) {
                    const float4 bv = *(const float4*)(v + 4 * u);
#pragma unroll
                    for (int p = 0; p < 4; p++) {
                        acc[p] = fmaf(bv.x, f1r[p][u].x, acc[p]);
                        acc[p] = fmaf(bv.y, f1r[p][u].y, acc[p]);
                        acc[p] = fmaf(bv.z, f1r[p][u].z, acc[p]);
                        acc[p] = fmaf(bv.w, f1r[p][u].w, acc[p]);
                    }
                }
#pragma unroll
                for (int d = 1; d < 16; d <<= 1) {
#pragma unroll
                    for (int p = 0; p < 4; p++)
                        acc[p] += __shfl_xor_sync(0xFFFFFFFFu, acc[p], d);
                }
                if ((lane & 15) == 0 && idx < n) {
#pragma unroll
                    for (int p = 0; p < 4; p++) {
                        if ((gm >> p) & 1) {
                            int ry = y - oy[p], rx = x - ox[p];
                            if ((unsigned)ry < 10u && (unsigned)rx < 10u)
                                D[warp][p][ry * 10 + rx] = acc[p];
                        }
                    }
                }
            }
            __syncwarp();
        }

        // ---- Phase B: taps for this level ----
#pragma unroll
        for (int p = 0; p < 4; p++) {
#pragma unroll
            for (int r = 0; r < 2; r++) {
                int l = lane + r * 32;
                if (l < NL) {
                    const float py = (ycf[p] + s_dy[l]) * s;
                    const float px = (xcf[p] + s_dx[l]) * s;
                    const float y0f = floorf(py);
                    const float x0f = floorf(px);
                    const float wy1 = py - y0f, wy0 = 1.0f - wy1;
                    const float wx1 = px - x0f, wx0 = 1.0f - wx1;
                    const int iy = (int)y0f - oy[p];
                    const int ix = (int)x0f - ox[p];
                    const float* Dk = D[warp][p];
                    const float d00 = Dk[iy * 10 + ix];
                    const float d01 = Dk[iy * 10 + ix + 1];
                    const float d10 = Dk[iy * 10 + ix + 10];
                    const float d11 = Dk[iy * 10 + ix + 11];
                    const float rr = wy0 * (wx0 * d00 + wx1 * d01)
                                   + wy1 * (wx0 * d10 + wx1 * d11);
                    out[(((size_t)bb * NPIX + ip[p] * W8 + jp[p]) * 4 + k) * NL + l]
                        = rr * 0.0625f;   // 1/sqrt(256)
                }
            }
        }
        __syncwarp();
        __syncthreads();   // keep block's warps level-synchronous (L1 locality)
    }
}

// ---------------------------------------------------------------------------
extern "C" void kernel_launch(void* const* d_in, const int* in_sizes, int n_in,
                              void* d_out, int out_size) {
    const float* feat1 = (const float*)d_in[0];
    const float* feat2 = (const float*)d_in[1];
    const float* flow  = (const float*)d_in[2];
    float* out = (float*)d_out;

    dim3 tgrid(NPIX / 32, CH / 32, BATCH);
    dim3 tblk(32, 8);
    transpose_kernel<<<tgrid, tblk>>>(feat1, 0, NPIX);
    transpose_kernel<<<tgrid, tblk>>>(feat2, 1, F2P_PIX);

    {
        int ho = 32;
        int threads = BATCH * ho * ho * 64;
        pool_kernel<<<threads / 256, 256>>>(LVL0_OFF, LVL1_OFF, ho);
    }
    {
        int ho = 16;
        int threads = BATCH * ho * ho * 64;
        pool_kernel<<<threads / 256, 256>>>(LVL1_OFF, LVL2_OFF, ho);
    }
    {
        int ho = 8;
        int threads = BATCH * ho * ho * 64;
        pool_kernel<<<threads / 256, 256>>>(LVL2_OFF, LVL3_OFF, ho);
    }

    dim3 lgrid(256, BATCH);
    lookup_kernel<<<lgrid, 128>>>(flow, out);
}